// round 11
// baseline (speedup 1.0000x reference)
#include <cuda_runtime.h>
#include <cuda_fp16.h>
#include <cstdint>

#define HID     256
#define MROWS   16
#define THREADS 256

// ---------------- smem byte offsets ----------------
// A: 6 planes x 8KB fp16 (hi c0..2, lo c0..2); each plane [kc 4][row 16][kk 64]
#define SM_A     0
#define SM_W     (6*8192)                // 2 x 32KB double-buffered W chunk [n 256][kk 64] fp16
#define SM_RED   (SM_W + 2*32768)        // 3ch x 16 rows x 8 colgroups floats
#define SM_TOTAL (SM_RED + 3*16*8*4)     // ~113.7 KB -> 2 CTAs/SM

// pre-rounded fp16, transposed, swizzled W2/W3: [layer*4+kc] tiles of 32KB
static __device__ uint4 g_Wsplit[8 * 2048];

// ---------------- helpers ----------------
__device__ __forceinline__ uint32_t s2u(const void* p) {
    uint32_t a;
    asm("{ .reg .u64 t; cvta.to.shared.u64 t, %1; cvt.u32.u64 %0, t; }" : "=r"(a) : "l"(p));
    return a;
}
__device__ __forceinline__ uint32_t sw128(uint32_t o) { return o ^ ((o >> 3) & 0x70); }

// float -> (fp16 hi, fp16 lo residual)
__device__ __forceinline__ uint32_t f2h(float v, uint32_t& lo) {
    __half h = __float2half_rn(v);
    float hv = __half2float(h);
    __half l = __float2half_rn(v - hv);
    lo = (uint32_t)__half_as_ushort(l);
    return (uint32_t)__half_as_ushort(h);
}
__device__ __forceinline__ void ldsm4(uint32_t r[4], uint32_t addr) {
    asm volatile("ldmatrix.sync.aligned.m8n8.x4.shared.b16 {%0,%1,%2,%3}, [%4];"
                 : "=r"(r[0]), "=r"(r[1]), "=r"(r[2]), "=r"(r[3]) : "r"(addr));
}
__device__ __forceinline__ void mma_fp16(float d[4], const uint32_t a[4],
                                         uint32_t b0, uint32_t b1) {
    asm volatile("mma.sync.aligned.m16n8k16.row.col.f32.f16.f16.f32 "
                 "{%0,%1,%2,%3}, {%4,%5,%6,%7}, {%8,%9}, {%0,%1,%2,%3};"
                 : "+f"(d[0]), "+f"(d[1]), "+f"(d[2]), "+f"(d[3])
                 : "r"(a[0]), "r"(a[1]), "r"(a[2]), "r"(a[3]), "r"(b0), "r"(b1));
}
__device__ __forceinline__ void sts32(uint32_t a, uint32_t v) {
    asm volatile("st.shared.b32 [%0], %1;" :: "r"(a), "r"(v) : "memory");
}
__device__ __forceinline__ void cpasync16(uint32_t dst, const void* src) {
    asm volatile("cp.async.cg.shared.global [%0], [%1], 16;" :: "r"(dst), "l"(src));
}

// ============ prep: round to fp16 + transpose + swizzle W2/W3 ============
__global__ void prep_kernel(const float* __restrict__ W2, const float* __restrict__ W3)
{
    int t = blockIdx.x * blockDim.x + threadIdx.x;   // 131072 threads
    int l = t >> 16;
    int r = t & 65535;
    int k = r >> 8, n = r & 255;                     // W[k][n]
    float v = (l == 0 ? W2 : W3)[k * HID + n];
    __half h = __float2half_rn(v);
    int kc = k >> 6, kk = k & 63;
    uint32_t woff = sw128((uint32_t)(n * 128 + kk * 2)) >> 1;
    uint16_t* th = (uint16_t*)&g_Wsplit[(size_t)(l * 4 + kc) * 2048];
    th[woff] = (uint16_t)__half_as_ushort(h);
}

// ============ fused PINN: layers 1-4, forward + d/dx0 + d2/dx0^2 ============
__global__ void __launch_bounds__(THREADS, 2)
pinn_tc_kernel(const float* __restrict__ x,  const float* __restrict__ W1,
               const float* __restrict__ b1, const float* __restrict__ b2,
               const float* __restrict__ b3, const float* __restrict__ W4,
               const float* __restrict__ b4, float* __restrict__ out, int Btot)
{
    extern __shared__ char smem[];
    uint32_t sb = s2u(smem);
    const int tid = threadIdx.x, lane = tid & 31, w = tid >> 5;
    const int gr0 = blockIdx.x * MROWS;

    // ---- prologue: async-prefetch W chunk 0 first (lands under layer-1 gen) ----
    {
        const uint4* src = &g_Wsplit[0];
        uint32_t dst = sb + SM_W + (uint32_t)tid * 16;
        #pragma unroll
        for (int i = 0; i < 8; i++) cpasync16(dst + i * 4096, src + tid + i * 256);
        asm volatile("cp.async.commit_group;" ::: "memory");
    }

    // ---------------- layer 1: closed-form triple -> A planes (fp16 hi/lo) ------
    {
        const int row  = tid >> 4;           // 0..15
        const int fseg = tid & 15;           // 16 feats each
        const float x0 = x[(gr0 + row) * 2 + 0];
        const float x1 = x[(gr0 + row) * 2 + 1];
        const int f0 = fseg * 16;
        const int kc = f0 >> 6;
        const uint32_t rowoff = sw128((uint32_t)(row * 128));
        #pragma unroll
        for (int i = 0; i < 16; i += 2) {
            uint32_t pk[6] = {0, 0, 0, 0, 0, 0};
            #pragma unroll
            for (int j = 0; j < 2; j++) {
                int f = f0 + i + j;
                float w0 = W1[f], w1 = W1[HID + f];
                float z = fmaf(x0, w0, fmaf(x1, w1, b1[f]));
                float th = tanhf(z);
                float u  = fmaf(-th, th, 1.0f);
                float v0 = th, v1 = u * w0, v2 = -2.0f * th * v1 * w0;
                uint32_t lo, hi;
                hi = f2h(v0, lo); pk[0] |= hi << (16 * j); pk[3] |= lo << (16 * j);
                hi = f2h(v1, lo); pk[1] |= hi << (16 * j); pk[4] |= lo << (16 * j);
                hi = f2h(v2, lo); pk[2] |= hi << (16 * j); pk[5] |= lo << (16 * j);
            }
            uint32_t off = sb + SM_A + kc * 2048 + (rowoff ^ (uint32_t)(((f0 + i) & 63) * 2));
            #pragma unroll
            for (int p = 0; p < 6; p++) sts32(off + p * 8192, pk[p]);
        }
    }

    // ------------- warp tiling (8 warps, M=16, each warp 32 N-cols) -------------
    const int cp = w;                        // col group: cp*32 .. +31
    const uint32_t m     = (uint32_t)(lane >> 3);
    const uint32_t rselA = (m & 1) * 8 + (lane & 7);     // 0..15
    const uint32_t kofA  = (uint32_t)(lane >> 4) * 8;
    const uint32_t aBase = sw128((uint32_t)(rselA * 128));
    const uint32_t nselB = (uint32_t)(lane >> 4) * 8 + (lane & 7);
    const uint32_t kofB  = (m & 1) * 8;
    uint32_t bBase[2];
    #pragma unroll
    for (int nf16 = 0; nf16 < 2; nf16++)
        bBase[nf16] = sw128((uint32_t)((cp * 32 + nf16 * 16 + nselB) * 128));

    const int r0 = lane >> 2;                // 0..7
    float s4[2][3] = {{0.f, 0.f, 0.f}, {0.f, 0.f, 0.f}};

    for (int layer = 0; layer < 2; layer++) {
        float acc[3][4][4];
        #pragma unroll
        for (int c = 0; c < 3; c++)
            #pragma unroll
            for (int nf = 0; nf < 4; nf++)
                #pragma unroll
                for (int q = 0; q < 4; q++) acc[c][nf][q] = 0.f;

        for (int kc = 0; kc < 4; kc++) {
            const int t = layer * 4 + kc;
            __syncthreads();             // prior reads of buf[(t+1)&1] done; A stores done
            if (t < 7) {                 // prefetch next chunk into other buffer
                const uint4* src = &g_Wsplit[(size_t)(t + 1) * 2048];
                uint32_t dst = sb + SM_W + (uint32_t)((t + 1) & 1) * 32768 + (uint32_t)tid * 16;
                #pragma unroll
                for (int i = 0; i < 8; i++) cpasync16(dst + i * 4096, src + tid + i * 256);
                asm volatile("cp.async.commit_group;" ::: "memory");
                asm volatile("cp.async.wait_group 1;" ::: "memory");
            } else {
                asm volatile("cp.async.wait_group 0;" ::: "memory");
            }
            __syncthreads();             // chunk t visible to all warps

            const uint32_t wbase = sb + SM_W + (uint32_t)(t & 1) * 32768;
            #pragma unroll
            for (int ks = 0; ks < 4; ks++) {
                const uint32_t kxA = (uint32_t)((ks * 16 + kofA) * 2);
                const uint32_t kxB = (uint32_t)((ks * 16 + kofB) * 2);
                uint32_t ah[3][4], al[3][4];
                const uint32_t abase = sb + SM_A + kc * 2048 + (aBase ^ kxA);
                #pragma unroll
                for (int c = 0; c < 3; c++) {
                    ldsm4(ah[c], abase + c * 8192);
                    ldsm4(al[c], abase + (3 + c) * 8192);
                }
                #pragma unroll
                for (int nf16 = 0; nf16 < 2; nf16++) {
                    uint32_t bh[4];
                    ldsm4(bh, wbase + (bBase[nf16] ^ kxB));
                    #pragma unroll
                    for (int c = 0; c < 3; c++) {
                        mma_fp16(acc[c][nf16 * 2],     ah[c], bh[0], bh[1]);
                        mma_fp16(acc[c][nf16 * 2],     al[c], bh[0], bh[1]);
                        mma_fp16(acc[c][nf16 * 2 + 1], ah[c], bh[2], bh[3]);
                        mma_fp16(acc[c][nf16 * 2 + 1], al[c], bh[2], bh[3]);
                    }
                }
            }
        }
        __syncthreads();    // all A reads done before epilogue overwrites A

        if (layer == 0) {
            // tanh triple rule -> write next A planes (fp16 hi/lo, in place)
            #pragma unroll
            for (int nf = 0; nf < 4; nf++) {
                int col = cp * 32 + nf * 8 + (lane & 3) * 2;
                #pragma unroll
                for (int half = 0; half < 2; half++) {
                    int row = r0 + half * 8;
                    uint32_t pk[6] = {0, 0, 0, 0, 0, 0};
                    #pragma unroll
                    for (int j = 0; j < 2; j++) {
                        float z  = acc[0][nf][half * 2 + j] + __ldg(&b2[col + j]);
                        float z1 = acc[1][nf][half * 2 + j];
                        float z2 = acc[2][nf][half * 2 + j];
                        float th = tanhf(z);
                        float u  = fmaf(-th, th, 1.0f);
                        float v0 = th, v1 = u * z1;
                        float v2 = fmaf(u, z2, -2.0f * th * v1 * z1);
                        uint32_t lo, hi;
                        hi = f2h(v0, lo); pk[0] |= hi << (16 * j); pk[3] |= lo << (16 * j);
                        hi = f2h(v1, lo); pk[1] |= hi << (16 * j); pk[4] |= lo << (16 * j);
                        hi = f2h(v2, lo); pk[2] |= hi << (16 * j); pk[5] |= lo << (16 * j);
                    }
                    uint32_t off = sb + SM_A + (col >> 6) * 2048 +
                                   sw128((uint32_t)(row * 128 + (col & 63) * 2));
                    #pragma unroll
                    for (int p = 0; p < 6; p++) sts32(off + p * 8192, pk[p]);
                }
            }
        } else {
            // tanh triple rule fused with layer-4 dot products (W4)
            #pragma unroll
            for (int nf = 0; nf < 4; nf++) {
                int col = cp * 32 + nf * 8 + (lane & 3) * 2;
                #pragma unroll
                for (int half = 0; half < 2; half++) {
                    #pragma unroll
                    for (int j = 0; j < 2; j++) {
                        float z  = acc[0][nf][half * 2 + j] + __ldg(&b3[col + j]);
                        float z1 = acc[1][nf][half * 2 + j];
                        float z2 = acc[2][nf][half * 2 + j];
                        float th = tanhf(z);
                        float u  = fmaf(-th, th, 1.0f);
                        float v0 = th, v1 = u * z1;
                        float v2 = fmaf(u, z2, -2.0f * th * v1 * z1);
                        float w4v = __ldg(&W4[col + j]);
                        s4[half][0] = fmaf(v0, w4v, s4[half][0]);
                        s4[half][1] = fmaf(v1, w4v, s4[half][1]);
                        s4[half][2] = fmaf(v2, w4v, s4[half][2]);
                    }
                }
            }
        }
    }

    // ---------------- layer-4 reduction ----------------
    #pragma unroll
    for (int half = 0; half < 2; half++)
        #pragma unroll
        for (int c = 0; c < 3; c++) {
            float v = s4[half][c];
            v += __shfl_xor_sync(0xffffffffu, v, 1);
            v += __shfl_xor_sync(0xffffffffu, v, 2);
            s4[half][c] = v;
        }
    float* red = (float*)(smem + SM_RED);
    if ((lane & 3) == 0) {
        int q  = lane >> 2;              // 0..7
        int ra = q, rb = q + 8;
        #pragma unroll
        for (int c = 0; c < 3; c++) {
            red[c * 128 + ra * 8 + cp] = s4[0][c];
            red[c * 128 + rb * 8 + cp] = s4[1][c];
        }
    }
    __syncthreads();
    if (tid < 48) {
        int ch = tid >> 4, row = tid & 15;
        float s = 0.f;
        #pragma unroll
        for (int g = 0; g < 8; g++) s += red[ch * 128 + row * 8 + g];
        if (ch == 0) s += b4[0];
        out[ch * Btot + gr0 + row] = s;
    }
}

extern "C" void kernel_launch(void* const* d_in, const int* in_sizes, int n_in,
                              void* d_out, int out_size)
{
    const float* x  = (const float*)d_in[0];
    const float* W1 = (const float*)d_in[1];
    const float* b1 = (const float*)d_in[2];
    const float* W2 = (const float*)d_in[3];
    const float* b2 = (const float*)d_in[4];
    const float* W3 = (const float*)d_in[5];
    const float* b3 = (const float*)d_in[6];
    const float* W4 = (const float*)d_in[7];
    const float* b4 = (const float*)d_in[8];
    float* out = (float*)d_out;

    int Btot = in_sizes[0] / 2;          // 131072
    int grid = Btot / MROWS;             // 8192 CTAs

    cudaFuncSetAttribute(pinn_tc_kernel,
                         cudaFuncAttributeMaxDynamicSharedMemorySize, SM_TOTAL);

    prep_kernel<<<512, 256>>>(W2, W3);
    pinn_tc_kernel<<<grid, THREADS, SM_TOTAL>>>(x, W1, b1, b2, b3, W4, b4, out, Btot);
}

// round 13
// speedup vs baseline: 1.2299x; 1.2299x over previous
#include <cuda_runtime.h>
#include <cuda_fp16.h>
#include <cstdint>

#define HID     256
#define MROWS   16
#define THREADS 256

// ---------------- smem byte offsets ----------------
// A: 6 planes x 8KB fp16 (hi c0..2, lo c0..2); each plane [kc 4][row 16][kk 64]
#define SM_A     0
#define SM_W     (6*8192)                // 2 x 32KB double-buffered W chunk [n 256][kk 64] fp16
#define SM_RED   SM_A                    // reduction overlaps A planes (A dead by then)
#define SM_TOTAL (SM_W + 2*32768)        // 114,688 B -> 2 CTAs/SM (231.4KB incl. reserve < 233.5KB)

// pre-rounded fp16, transposed, swizzled W2/W3: [layer*4+kc] tiles of 32KB
static __device__ uint4 g_Wsplit[8 * 2048];

// ---------------- helpers ----------------
__device__ __forceinline__ uint32_t s2u(const void* p) {
    uint32_t a;
    asm("{ .reg .u64 t; cvta.to.shared.u64 t, %1; cvt.u32.u64 %0, t; }" : "=r"(a) : "l"(p));
    return a;
}
__device__ __forceinline__ uint32_t sw128(uint32_t o) { return o ^ ((o >> 3) & 0x70); }

// float -> (fp16 hi, fp16 lo residual)
__device__ __forceinline__ uint32_t f2h(float v, uint32_t& lo) {
    __half h = __float2half_rn(v);
    float hv = __half2float(h);
    __half l = __float2half_rn(v - hv);
    lo = (uint32_t)__half_as_ushort(l);
    return (uint32_t)__half_as_ushort(h);
}
__device__ __forceinline__ void ldsm4(uint32_t r[4], uint32_t addr) {
    asm volatile("ldmatrix.sync.aligned.m8n8.x4.shared.b16 {%0,%1,%2,%3}, [%4];"
                 : "=r"(r[0]), "=r"(r[1]), "=r"(r[2]), "=r"(r[3]) : "r"(addr));
}
__device__ __forceinline__ void mma_fp16(float d[4], const uint32_t a[4],
                                         uint32_t b0, uint32_t b1) {
    asm volatile("mma.sync.aligned.m16n8k16.row.col.f32.f16.f16.f32 "
                 "{%0,%1,%2,%3}, {%4,%5,%6,%7}, {%8,%9}, {%0,%1,%2,%3};"
                 : "+f"(d[0]), "+f"(d[1]), "+f"(d[2]), "+f"(d[3])
                 : "r"(a[0]), "r"(a[1]), "r"(a[2]), "r"(a[3]), "r"(b0), "r"(b1));
}
__device__ __forceinline__ void sts32(uint32_t a, uint32_t v) {
    asm volatile("st.shared.b32 [%0], %1;" :: "r"(a), "r"(v) : "memory");
}
__device__ __forceinline__ void cpasync16(uint32_t dst, const void* src) {
    asm volatile("cp.async.cg.shared.global [%0], [%1], 16;" :: "r"(dst), "l"(src));
}

// ============ prep: round to fp16 + transpose + swizzle W2/W3 ============
__global__ void prep_kernel(const float* __restrict__ W2, const float* __restrict__ W3)
{
    int t = blockIdx.x * blockDim.x + threadIdx.x;   // 131072 threads
    int l = t >> 16;
    int r = t & 65535;
    int k = r >> 8, n = r & 255;                     // W[k][n]
    float v = (l == 0 ? W2 : W3)[k * HID + n];
    __half h = __float2half_rn(v);
    int kc = k >> 6, kk = k & 63;
    uint32_t woff = sw128((uint32_t)(n * 128 + kk * 2)) >> 1;
    uint16_t* th = (uint16_t*)&g_Wsplit[(size_t)(l * 4 + kc) * 2048];
    th[woff] = (uint16_t)__half_as_ushort(h);
}

// ============ fused PINN: layers 1-4, forward + d/dx0 + d2/dx0^2 ============
__global__ void __launch_bounds__(THREADS, 2)
pinn_tc_kernel(const float* __restrict__ x,  const float* __restrict__ W1,
               const float* __restrict__ b1, const float* __restrict__ b2,
               const float* __restrict__ b3, const float* __restrict__ W4,
               const float* __restrict__ b4, float* __restrict__ out, int Btot)
{
    extern __shared__ char smem[];
    uint32_t sb = s2u(smem);
    const int tid = threadIdx.x, lane = tid & 31, w = tid >> 5;
    const int gr0 = blockIdx.x * MROWS;

    // ---- prologue: async-prefetch W chunk 0 first (lands under layer-1 gen) ----
    {
        const uint4* src = &g_Wsplit[0];
        uint32_t dst = sb + SM_W + (uint32_t)tid * 16;
        #pragma unroll
        for (int i = 0; i < 8; i++) cpasync16(dst + i * 4096, src + tid + i * 256);
        asm volatile("cp.async.commit_group;" ::: "memory");
    }

    // ---------------- layer 1: closed-form triple -> A planes (fp16 hi/lo) ------
    {
        const int row  = tid >> 4;           // 0..15
        const int fseg = tid & 15;           // 16 feats each
        const float x0 = x[(gr0 + row) * 2 + 0];
        const float x1 = x[(gr0 + row) * 2 + 1];
        const int f0 = fseg * 16;
        const int kc = f0 >> 6;
        const uint32_t rowoff = sw128((uint32_t)(row * 128));
        #pragma unroll
        for (int i = 0; i < 16; i += 2) {
            uint32_t pk[6] = {0, 0, 0, 0, 0, 0};
            #pragma unroll
            for (int j = 0; j < 2; j++) {
                int f = f0 + i + j;
                float w0 = W1[f], w1 = W1[HID + f];
                float z = fmaf(x0, w0, fmaf(x1, w1, b1[f]));
                float th = tanhf(z);
                float u  = fmaf(-th, th, 1.0f);
                float v0 = th, v1 = u * w0, v2 = -2.0f * th * v1 * w0;
                uint32_t lo, hi;
                hi = f2h(v0, lo); pk[0] |= hi << (16 * j); pk[3] |= lo << (16 * j);
                hi = f2h(v1, lo); pk[1] |= hi << (16 * j); pk[4] |= lo << (16 * j);
                hi = f2h(v2, lo); pk[2] |= hi << (16 * j); pk[5] |= lo << (16 * j);
            }
            uint32_t off = sb + SM_A + kc * 2048 + (rowoff ^ (uint32_t)(((f0 + i) & 63) * 2));
            #pragma unroll
            for (int p = 0; p < 6; p++) sts32(off + p * 8192, pk[p]);
        }
    }

    // ------------- warp tiling (8 warps, M=16, each warp 32 N-cols) -------------
    const int cp = w;                        // col group: cp*32 .. +31
    const uint32_t m     = (uint32_t)(lane >> 3);
    const uint32_t rselA = (m & 1) * 8 + (lane & 7);     // 0..15
    const uint32_t kofA  = (uint32_t)(lane >> 4) * 8;
    const uint32_t aBase = sw128((uint32_t)(rselA * 128));
    const uint32_t nselB = (uint32_t)(lane >> 4) * 8 + (lane & 7);
    const uint32_t kofB  = (m & 1) * 8;
    uint32_t bBase[2];
    #pragma unroll
    for (int nf16 = 0; nf16 < 2; nf16++)
        bBase[nf16] = sw128((uint32_t)((cp * 32 + nf16 * 16 + nselB) * 128));

    const int r0 = lane >> 2;                // 0..7
    float s4[2][3] = {{0.f, 0.f, 0.f}, {0.f, 0.f, 0.f}};

    for (int layer = 0; layer < 2; layer++) {
        float acc[3][4][4];
        #pragma unroll
        for (int c = 0; c < 3; c++)
            #pragma unroll
            for (int nf = 0; nf < 4; nf++)
                #pragma unroll
                for (int q = 0; q < 4; q++) acc[c][nf][q] = 0.f;

        for (int kc = 0; kc < 4; kc++) {
            const int t = layer * 4 + kc;
            __syncthreads();             // prior reads of buf[(t+1)&1] done; A stores done
            if (t < 7) {                 // prefetch next chunk into other buffer
                const uint4* src = &g_Wsplit[(size_t)(t + 1) * 2048];
                uint32_t dst = sb + SM_W + (uint32_t)((t + 1) & 1) * 32768 + (uint32_t)tid * 16;
                #pragma unroll
                for (int i = 0; i < 8; i++) cpasync16(dst + i * 4096, src + tid + i * 256);
                asm volatile("cp.async.commit_group;" ::: "memory");
                asm volatile("cp.async.wait_group 1;" ::: "memory");
            } else {
                asm volatile("cp.async.wait_group 0;" ::: "memory");
            }
            __syncthreads();             // chunk t visible to all warps

            const uint32_t wbase = sb + SM_W + (uint32_t)(t & 1) * 32768;
            #pragma unroll
            for (int ks = 0; ks < 4; ks++) {
                const uint32_t kxA = (uint32_t)((ks * 16 + kofA) * 2);
                const uint32_t kxB = (uint32_t)((ks * 16 + kofB) * 2);
                uint32_t ah[3][4], al[3][4];
                const uint32_t abase = sb + SM_A + kc * 2048 + (aBase ^ kxA);
                #pragma unroll
                for (int c = 0; c < 3; c++) {
                    ldsm4(ah[c], abase + c * 8192);
                    ldsm4(al[c], abase + (3 + c) * 8192);
                }
                #pragma unroll
                for (int nf16 = 0; nf16 < 2; nf16++) {
                    uint32_t bh[4];
                    ldsm4(bh, wbase + (bBase[nf16] ^ kxB));
                    #pragma unroll
                    for (int c = 0; c < 3; c++) {
                        mma_fp16(acc[c][nf16 * 2],     ah[c], bh[0], bh[1]);
                        mma_fp16(acc[c][nf16 * 2],     al[c], bh[0], bh[1]);
                        mma_fp16(acc[c][nf16 * 2 + 1], ah[c], bh[2], bh[3]);
                        mma_fp16(acc[c][nf16 * 2 + 1], al[c], bh[2], bh[3]);
                    }
                }
            }
        }
        __syncthreads();    // all A reads done before epilogue overwrites A

        if (layer == 0) {
            // tanh triple rule -> write next A planes (fp16 hi/lo, in place)
            #pragma unroll
            for (int nf = 0; nf < 4; nf++) {
                int col = cp * 32 + nf * 8 + (lane & 3) * 2;
                #pragma unroll
                for (int half = 0; half < 2; half++) {
                    int row = r0 + half * 8;
                    uint32_t pk[6] = {0, 0, 0, 0, 0, 0};
                    #pragma unroll
                    for (int j = 0; j < 2; j++) {
                        float z  = acc[0][nf][half * 2 + j] + __ldg(&b2[col + j]);
                        float z1 = acc[1][nf][half * 2 + j];
                        float z2 = acc[2][nf][half * 2 + j];
                        float th = tanhf(z);
                        float u  = fmaf(-th, th, 1.0f);
                        float v0 = th, v1 = u * z1;
                        float v2 = fmaf(u, z2, -2.0f * th * v1 * z1);
                        uint32_t lo, hi;
                        hi = f2h(v0, lo); pk[0] |= hi << (16 * j); pk[3] |= lo << (16 * j);
                        hi = f2h(v1, lo); pk[1] |= hi << (16 * j); pk[4] |= lo << (16 * j);
                        hi = f2h(v2, lo); pk[2] |= hi << (16 * j); pk[5] |= lo << (16 * j);
                    }
                    uint32_t off = sb + SM_A + (col >> 6) * 2048 +
                                   sw128((uint32_t)(row * 128 + (col & 63) * 2));
                    #pragma unroll
                    for (int p = 0; p < 6; p++) sts32(off + p * 8192, pk[p]);
                }
            }
        } else {
            // tanh triple rule fused with layer-4 dot products (W4)
            #pragma unroll
            for (int nf = 0; nf < 4; nf++) {
                int col = cp * 32 + nf * 8 + (lane & 3) * 2;
                #pragma unroll
                for (int half = 0; half < 2; half++) {
                    #pragma unroll
                    for (int j = 0; j < 2; j++) {
                        float z  = acc[0][nf][half * 2 + j] + __ldg(&b3[col + j]);
                        float z1 = acc[1][nf][half * 2 + j];
                        float z2 = acc[2][nf][half * 2 + j];
                        float th = tanhf(z);
                        float u  = fmaf(-th, th, 1.0f);
                        float v0 = th, v1 = u * z1;
                        float v2 = fmaf(u, z2, -2.0f * th * v1 * z1);
                        float w4v = __ldg(&W4[col + j]);
                        s4[half][0] = fmaf(v0, w4v, s4[half][0]);
                        s4[half][1] = fmaf(v1, w4v, s4[half][1]);
                        s4[half][2] = fmaf(v2, w4v, s4[half][2]);
                    }
                }
            }
        }
    }

    // ---------------- layer-4 reduction (red overlaps dead A planes) ----------------
    #pragma unroll
    for (int half = 0; half < 2; half++)
        #pragma unroll
        for (int c = 0; c < 3; c++) {
            float v = s4[half][c];
            v += __shfl_xor_sync(0xffffffffu, v, 1);
            v += __shfl_xor_sync(0xffffffffu, v, 2);
            s4[half][c] = v;
        }
    __syncthreads();    // layer-1 epilogue done everywhere before red overwrites A region
    float* red = (float*)(smem + SM_RED);
    if ((lane & 3) == 0) {
        int q  = lane >> 2;              // 0..7
        int ra = q, rb = q + 8;
        #pragma unroll
        for (int c = 0; c < 3; c++) {
            red[c * 128 + ra * 8 + cp] = s4[0][c];
            red[c * 128 + rb * 8 + cp] = s4[1][c];
        }
    }
    __syncthreads();
    if (tid < 48) {
        int ch = tid >> 4, row = tid & 15;
        float s = 0.f;
        #pragma unroll
        for (int g = 0; g < 8; g++) s += red[ch * 128 + row * 8 + g];
        if (ch == 0) s += b4[0];
        out[ch * Btot + gr0 + row] = s;
    }
}

extern "C" void kernel_launch(void* const* d_in, const int* in_sizes, int n_in,
                              void* d_out, int out_size)
{
    const float* x  = (const float*)d_in[0];
    const float* W1 = (const float*)d_in[1];
    const float* b1 = (const float*)d_in[2];
    const float* W2 = (const float*)d_in[3];
    const float* b2 = (const float*)d_in[4];
    const float* W3 = (const float*)d_in[5];
    const float* b3 = (const float*)d_in[6];
    const float* W4 = (const float*)d_in[7];
    const float* b4 = (const float*)d_in[8];
    float* out = (float*)d_out;

    int Btot = in_sizes[0] / 2;          // 131072
    int grid = Btot / MROWS;             // 8192 CTAs

    cudaFuncSetAttribute(pinn_tc_kernel,
                         cudaFuncAttributeMaxDynamicSharedMemorySize, SM_TOTAL);

    prep_kernel<<<512, 256>>>(W2, W3);
    pinn_tc_kernel<<<grid, THREADS, SM_TOTAL>>>(x, W1, b1, b2, b3, W4, b4, out, Btot);
}

// round 16
// speedup vs baseline: 1.2962x; 1.0539x over previous
#include <cuda_runtime.h>
#include <cuda_fp16.h>
#include <cstdint>

#define HID     256
#define MROWS   16
#define THREADS 256

// ---------------- smem ----------------
// A: 6 planes x 8KB fp16 (hi c0..2, lo c0..2); each plane [kc 4][row 16][kk 64]
#define SM_A     0
#define SM_RED   SM_A                    // reduction overlaps A planes (A dead by then)
#define SM_TOTAL (6*8192)                // 48KB -> 2 CTAs/SM (reg-limited)

// W2/W3 pre-rounded to fp16 in mma m16n8k16 B-fragment lane order.
// Flat u32 index t (per layer 32768 u32):
//   rr = t&3, lane = (t>>2)&31, j = (t>>7)&1, s = (t>>8)&15, g = (t>>12)&7, l = t>>15
//   nf8 = j*2 + rr/2, q = rr&1
//   n = g*32 + nf8*8 + lane/4 ;  k = s*16 + (lane%4)*2 + q*8
//   u32 = fp16(W[k][n]) | fp16(W[k+1][n]) << 16   (PTX B-frag: {B[2t][n],B[2t+1][n]}, second reg k+8)
static __device__ uint4 g_Wfrag[16384];   // 2 layers x 8192 uint4 = 256 KB

// ---------------- helpers ----------------
__device__ __forceinline__ uint32_t s2u(const void* p) {
    uint32_t a;
    asm("{ .reg .u64 t; cvta.to.shared.u64 t, %1; cvt.u32.u64 %0, t; }" : "=r"(a) : "l"(p));
    return a;
}
__device__ __forceinline__ uint32_t sw128(uint32_t o) { return o ^ ((o >> 3) & 0x70); }

// float -> (fp16 hi, fp16 lo residual)
__device__ __forceinline__ uint32_t f2h(float v, uint32_t& lo) {
    __half h = __float2half_rn(v);
    float hv = __half2float(h);
    __half l = __float2half_rn(v - hv);
    lo = (uint32_t)__half_as_ushort(l);
    return (uint32_t)__half_as_ushort(h);
}
__device__ __forceinline__ void ldsm4(uint32_t r[4], uint32_t addr) {
    asm volatile("ldmatrix.sync.aligned.m8n8.x4.shared.b16 {%0,%1,%2,%3}, [%4];"
                 : "=r"(r[0]), "=r"(r[1]), "=r"(r[2]), "=r"(r[3]) : "r"(addr));
}
__device__ __forceinline__ void mma_fp16(float d[4], const uint32_t a[4],
                                         uint32_t b0, uint32_t b1) {
    asm volatile("mma.sync.aligned.m16n8k16.row.col.f32.f16.f16.f32 "
                 "{%0,%1,%2,%3}, {%4,%5,%6,%7}, {%8,%9}, {%0,%1,%2,%3};"
                 : "+f"(d[0]), "+f"(d[1]), "+f"(d[2]), "+f"(d[3])
                 : "r"(a[0]), "r"(a[1]), "r"(a[2]), "r"(a[3]), "r"(b0), "r"(b1));
}
__device__ __forceinline__ void sts32(uint32_t a, uint32_t v) {
    asm volatile("st.shared.b32 [%0], %1;" :: "r"(a), "r"(v) : "memory");
}

// ============ prep: W2/W3 -> fp16 B-fragment lane-order tiles ============
__global__ void prep_kernel(const float* __restrict__ W2, const float* __restrict__ W3)
{
    int t = blockIdx.x * blockDim.x + threadIdx.x;   // 65536 threads, one u32 each
    int rr   = t & 3;
    int lane = (t >> 2) & 31;
    int j    = (t >> 7) & 1;
    int s    = (t >> 8) & 15;
    int g    = (t >> 12) & 7;
    int l    = t >> 15;
    int nf8 = j * 2 + (rr >> 1);
    int q   = rr & 1;
    int n = g * 32 + nf8 * 8 + (lane >> 2);
    int k = s * 16 + (lane & 3) * 2 + q * 8;
    const float* W = l ? W3 : W2;
    uint32_t lo = (uint32_t)__half_as_ushort(__float2half_rn(W[k * HID + n]));
    uint32_t hi = (uint32_t)__half_as_ushort(__float2half_rn(W[(k + 1) * HID + n]));
    ((uint32_t*)g_Wfrag)[t] = lo | (hi << 16);
}

// ============ fused PINN: layers 1-4, forward + d/dx0 + d2/dx0^2 ============
__global__ void __launch_bounds__(THREADS, 2)
pinn_tc_kernel(const float* __restrict__ x,  const float* __restrict__ W1,
               const float* __restrict__ b1, const float* __restrict__ b2,
               const float* __restrict__ b3, const float* __restrict__ W4,
               const float* __restrict__ b4, float* __restrict__ out, int Btot)
{
    extern __shared__ char smem[];
    uint32_t sb = s2u(smem);
    const int tid = threadIdx.x, lane = tid & 31, w = tid >> 5;
    const int gr0 = blockIdx.x * MROWS;

    // ---------------- layer 1: closed-form triple -> A planes (fp16 hi/lo) ------
    {
        const int row  = tid >> 4;           // 0..15
        const int fseg = tid & 15;           // 16 feats each
        const float x0 = x[(gr0 + row) * 2 + 0];
        const float x1 = x[(gr0 + row) * 2 + 1];
        const int f0 = fseg * 16;
        const int kc = f0 >> 6;
        const uint32_t rowoff = sw128((uint32_t)(row * 128));
        #pragma unroll
        for (int i = 0; i < 16; i += 2) {
            uint32_t pk[6] = {0, 0, 0, 0, 0, 0};
            #pragma unroll
            for (int j = 0; j < 2; j++) {
                int f = f0 + i + j;
                float w0 = W1[f], w1 = W1[HID + f];
                float z = fmaf(x0, w0, fmaf(x1, w1, b1[f]));
                float th = tanhf(z);
                float u  = fmaf(-th, th, 1.0f);
                float v0 = th, v1 = u * w0, v2 = -2.0f * th * v1 * w0;
                uint32_t lo, hi;
                hi = f2h(v0, lo); pk[0] |= hi << (16 * j); pk[3] |= lo << (16 * j);
                hi = f2h(v1, lo); pk[1] |= hi << (16 * j); pk[4] |= lo << (16 * j);
                hi = f2h(v2, lo); pk[2] |= hi << (16 * j); pk[5] |= lo << (16 * j);
            }
            uint32_t off = sb + SM_A + kc * 2048 + (rowoff ^ (uint32_t)(((f0 + i) & 63) * 2));
            #pragma unroll
            for (int p = 0; p < 6; p++) sts32(off + p * 8192, pk[p]);
        }
    }
    __syncthreads();     // A planes visible to all warps

    // ------------- warp tiling (8 warps, M=16, each warp 32 N-cols) -------------
    const int cp = w;                        // col group: cp*32 .. +31
    const uint32_t m     = (uint32_t)(lane >> 3);
    const uint32_t rselA = (m & 1) * 8 + (lane & 7);     // 0..15
    const uint32_t kofA  = (uint32_t)(lane >> 4) * 8;
    const uint32_t aBase = sw128((uint32_t)(rselA * 128));

    const int r0 = lane >> 2;                // 0..7
    float s4[2][3] = {{0.f, 0.f, 0.f}, {0.f, 0.f, 0.f}};

    for (int layer = 0; layer < 2; layer++) {
        float acc[3][4][4];
        #pragma unroll
        for (int c = 0; c < 3; c++)
            #pragma unroll
            for (int nf = 0; nf < 4; nf++)
                #pragma unroll
                for (int q = 0; q < 4; q++) acc[c][nf][q] = 0.f;

        const uint4* wf = &g_Wfrag[(size_t)(layer * 8 + cp) * 1024];

        // register-double-buffered B-frags, one K-step ahead; NO barriers in loop
        uint4 b0 = __ldg(&wf[lane]);
        uint4 b1 = __ldg(&wf[32 + lane]);
        #pragma unroll 4
        for (int s = 0; s < 16; s++) {
            const int sn = (s + 1) & 15;                  // wrap: always-valid prefetch
            uint4 nb0 = __ldg(&wf[sn * 64 + lane]);
            uint4 nb1 = __ldg(&wf[sn * 64 + 32 + lane]);

            const int kc = s >> 2, ks = s & 3;
            const uint32_t kxA = (uint32_t)((ks * 16 + kofA) * 2);
            uint32_t ah[3][4], al[3][4];
            const uint32_t abase = sb + SM_A + kc * 2048 + (aBase ^ kxA);
            #pragma unroll
            for (int c = 0; c < 3; c++) {
                ldsm4(ah[c], abase + c * 8192);
                ldsm4(al[c], abase + (3 + c) * 8192);
            }
            #pragma unroll
            for (int c = 0; c < 3; c++) {
                mma_fp16(acc[c][0], ah[c], b0.x, b0.y);
                mma_fp16(acc[c][0], al[c], b0.x, b0.y);
                mma_fp16(acc[c][1], ah[c], b0.z, b0.w);
                mma_fp16(acc[c][1], al[c], b0.z, b0.w);
                mma_fp16(acc[c][2], ah[c], b1.x, b1.y);
                mma_fp16(acc[c][2], al[c], b1.x, b1.y);
                mma_fp16(acc[c][3], ah[c], b1.z, b1.w);
                mma_fp16(acc[c][3], al[c], b1.z, b1.w);
            }
            b0 = nb0; b1 = nb1;
        }
        __syncthreads();    // all A reads done before epilogue overwrites A

        if (layer == 0) {
            // tanh triple rule -> write next A planes (fp16 hi/lo, in place)
            #pragma unroll
            for (int nf = 0; nf < 4; nf++) {
                int col = cp * 32 + nf * 8 + (lane & 3) * 2;
                #pragma unroll
                for (int half = 0; half < 2; half++) {
                    int row = r0 + half * 8;
                    uint32_t pk[6] = {0, 0, 0, 0, 0, 0};
                    #pragma unroll
                    for (int j = 0; j < 2; j++) {
                        float z  = acc[0][nf][half * 2 + j] + __ldg(&b2[col + j]);
                        float z1 = acc[1][nf][half * 2 + j];
                        float z2 = acc[2][nf][half * 2 + j];
                        float th = tanhf(z);
                        float u  = fmaf(-th, th, 1.0f);
                        float v0 = th, v1 = u * z1;
                        float v2 = fmaf(u, z2, -2.0f * th * v1 * z1);
                        uint32_t lo, hi;
                        hi = f2h(v0, lo); pk[0] |= hi << (16 * j); pk[3] |= lo << (16 * j);
                        hi = f2h(v1, lo); pk[1] |= hi << (16 * j); pk[4] |= lo << (16 * j);
                        hi = f2h(v2, lo); pk[2] |= hi << (16 * j); pk[5] |= lo << (16 * j);
                    }
                    uint32_t off = sb + SM_A + (col >> 6) * 2048 +
                                   sw128((uint32_t)(row * 128 + (col & 63) * 2));
                    #pragma unroll
                    for (int p = 0; p < 6; p++) sts32(off + p * 8192, pk[p]);
                }
            }
            __syncthreads();    // new A planes visible before layer-1 mainloop
        } else {
            // tanh triple rule fused with layer-4 dot products (W4)
            #pragma unroll
            for (int nf = 0; nf < 4; nf++) {
                int col = cp * 32 + nf * 8 + (lane & 3) * 2;
                #pragma unroll
                for (int half = 0; half < 2; half++) {
                    #pragma unroll
                    for (int j = 0; j < 2; j++) {
                        float z  = acc[0][nf][half * 2 + j] + __ldg(&b3[col + j]);
                        float z1 = acc[1][nf][half * 2 + j];
                        float z2 = acc[2][nf][half * 2 + j];
                        float th = tanhf(z);
                        float u  = fmaf(-th, th, 1.0f);
                        float v0 = th, v1 = u * z1;
                        float v2 = fmaf(u, z2, -2.0f * th * v1 * z1);
                        float w4v = __ldg(&W4[col + j]);
                        s4[half][0] = fmaf(v0, w4v, s4[half][0]);
                        s4[half][1] = fmaf(v1, w4v, s4[half][1]);
                        s4[half][2] = fmaf(v2, w4v, s4[half][2]);
                    }
                }
            }
        }
    }

    // ---------------- layer-4 reduction (red overlaps dead A planes) ----------------
    #pragma unroll
    for (int half = 0; half < 2; half++)
        #pragma unroll
        for (int c = 0; c < 3; c++) {
            float v = s4[half][c];
            v += __shfl_xor_sync(0xffffffffu, v, 1);
            v += __shfl_xor_sync(0xffffffffu, v, 2);
            s4[half][c] = v;
        }
    __syncthreads();    // mainloop A reads done before red overwrites A region
    float* red = (float*)(smem + SM_RED);
    if ((lane & 3) == 0) {
        int q  = lane >> 2;              // 0..7
        int ra = q, rb = q + 8;
        #pragma unroll
        for (int c = 0; c < 3; c++) {
            red[c * 128 + ra * 8 + cp] = s4[0][c];
            red[c * 128 + rb * 8 + cp] = s4[1][c];
        }
    }
    __syncthreads();
    if (tid < 48) {
        int ch = tid >> 4, row = tid & 15;
        float s = 0.f;
        #pragma unroll
        for (int g = 0; g < 8; g++) s += red[ch * 128 + row * 8 + g];
        if (ch == 0) s += b4[0];
        out[ch * Btot + gr0 + row] = s;
    }
}

extern "C" void kernel_launch(void* const* d_in, const int* in_sizes, int n_in,
                              void* d_out, int out_size)
{
    const float* x  = (const float*)d_in[0];
    const float* W1 = (const float*)d_in[1];
    const float* b1 = (const float*)d_in[2];
    const float* W2 = (const float*)d_in[3];
    const float* b2 = (const float*)d_in[4];
    const float* W3 = (const float*)d_in[5];
    const float* b3 = (const float*)d_in[6];
    const float* W4 = (const float*)d_in[7];
    const float* b4 = (const float*)d_in[8];
    float* out = (float*)d_out;

    int Btot = in_sizes[0] / 2;          // 131072
    int grid = Btot / MROWS;             // 8192 CTAs

    cudaFuncSetAttribute(pinn_tc_kernel,
                         cudaFuncAttributeMaxDynamicSharedMemorySize, SM_TOTAL);

    prep_kernel<<<256, 256>>>(W2, W3);   // 65536 threads: one u32 each
    pinn_tc_kernel<<<grid, THREADS, SM_TOTAL>>>(x, W1, b1, b2, b3, W4, b4, out, Btot);
}